// round 1
// baseline (speedup 1.0000x reference)
#include <cuda_runtime.h>
#include <cstdint>
#include <cstddef>

// ---------------------------------------------------------------------------
// TreeLSTM on complete binary trees.
//   B=256 trees, 256 leaves each (511 nodes), H=512, X=300, 5 classes.
// h/c stored [B, 511, H] leaves-first; children of level-l node j are the
// contiguous pair (2j, 2j+1) of level l-1 -> h_cat is 1024 contiguous floats.
// ---------------------------------------------------------------------------

#define B_   256
#define LVS  256
#define H_   512
#define X_   300
#define XP   304          // X padded to multiple of 8 (K tiling)
#define NN   511
#define TH   1536         // 3*H
#define NC   2560         // 1536 (U_iou) + 1024 (U_f)

// -------------------- static scratch (no allocations allowed) ---------------
__device__ float g_h  [(size_t)B_ * NN * H_];        // 268 MB
__device__ float g_c  [(size_t)B_ * NN * H_];        // 268 MB
__device__ float g_buf[(size_t)B_ * LVS * TH];       // 403 MB (>= 32768*2560)
__device__ float g_x  [(size_t)B_ * LVS * XP];       // gathered+padded leaf inputs
__device__ float g_wc [1024 * NC];                   // packed [K=1024, N=2560], K-major rows
__device__ float g_wl [XP * TH];                     // packed leaf W [K=304, N=1536]
__device__ float g_bc [NC];                          // packed bias

// -------------------- f32x2 packed-math helpers -----------------------------
__device__ __forceinline__ unsigned long long dup2(float x) {
    unsigned long long r;
    asm("mov.b64 %0, {%1, %1};" : "=l"(r) : "f"(x));
    return r;
}
__device__ __forceinline__ unsigned long long pack2(float x, float y) {
    unsigned long long r;
    asm("mov.b64 %0, {%1, %2};" : "=l"(r) : "f"(x), "f"(y));
    return r;
}
__device__ __forceinline__ void unpack2(unsigned long long v, float& x, float& y) {
    asm("mov.b64 {%0, %1}, %2;" : "=f"(x), "=f"(y) : "l"(v));
}
__device__ __forceinline__ void ffma2(unsigned long long& d,
                                      unsigned long long a, unsigned long long b) {
    asm("fma.rn.f32x2 %0, %1, %2, %0;" : "+l"(d) : "l"(a), "l"(b));
}

// -------------------- SGEMM: C[M,N] = A[M,K] @ Bw[K,N] + bias ---------------
// BM=BN=128, BK=8, 256 threads, 8x8 micro-tile as 8x4 f32x2 pairs.
// tree_lm >= 0: row r maps to h_cat of tree node (b = r>>tree_lm,
//               j = r & (m-1)) -> contiguous 1024 floats in g_h.
// tree_lm < 0 : plain row-major A with stride lda.
__global__ void __launch_bounds__(256, 2) sgemm_kernel(
    const float* __restrict__ A, const float* __restrict__ Bw,
    const float* __restrict__ bias, float* __restrict__ C,
    int N, int K, int lda, int tree_lm, int off_prev)
{
    __shared__ float As[8][128];
    __shared__ float Bs[8][128];

    const int tid = threadIdx.x;
    const int m0 = blockIdx.y * 128, n0 = blockIdx.x * 128;

    // A-tile loader: each thread loads one float4 (row = tid/2, seg = tid&1)
    const int arow = tid >> 1;
    const int acol = (tid & 1) * 4;
    const int r = m0 + arow;
    const float* Arow;
    if (tree_lm >= 0) {
        const int b = r >> tree_lm;
        const int j = r & ((1 << tree_lm) - 1);
        Arow = A + ((size_t)b * NN + off_prev + 2 * j) * H_;
    } else {
        Arow = A + (size_t)r * lda;
    }
    // B-tile loader
    const int brow = tid >> 5;
    const int bcol = (tid & 31) * 4;
    const float* Bp = Bw + (size_t)brow * N + n0 + bcol;

    unsigned long long acc[8][4];
#pragma unroll
    for (int i = 0; i < 8; i++)
#pragma unroll
        for (int j = 0; j < 4; j++) acc[i][j] = 0ull;

    const int tx = tid & 15, ty = tid >> 4;

    for (int k0 = 0; k0 < K; k0 += 8) {
        float4 av = *(const float4*)(Arow + k0 + acol);
        As[acol + 0][arow] = av.x;
        As[acol + 1][arow] = av.y;
        As[acol + 2][arow] = av.z;
        As[acol + 3][arow] = av.w;
        float4 bv = *(const float4*)(Bp + (size_t)k0 * N);
        *(float4*)&Bs[brow][bcol] = bv;
        __syncthreads();
#pragma unroll
        for (int kk = 0; kk < 8; kk++) {
            unsigned long long a2[8], b2[4];
#pragma unroll
            for (int i = 0; i < 8; i++) a2[i] = dup2(As[kk][ty + 16 * i]);
#pragma unroll
            for (int j = 0; j < 4; j++) {
                float2 v = *(const float2*)&Bs[kk][2 * tx + 32 * j];
                b2[j] = pack2(v.x, v.y);
            }
#pragma unroll
            for (int i = 0; i < 8; i++)
#pragma unroll
                for (int j = 0; j < 4; j++) ffma2(acc[i][j], a2[i], b2[j]);
        }
        __syncthreads();
    }

#pragma unroll
    for (int i = 0; i < 8; i++) {
        const size_t rr = (size_t)(m0 + ty + 16 * i);
#pragma unroll
        for (int j = 0; j < 4; j++) {
            const int cc = n0 + 2 * tx + 32 * j;
            float x, y;
            unpack2(acc[i][j], x, y);
            float2 o;
            o.x = x + bias[cc];
            o.y = y + bias[cc + 1];
            *(float2*)&C[rr * (size_t)N + cc] = o;
        }
    }
}

// -------------------- cell / epilogue kernels -------------------------------
__device__ __forceinline__ float sigf(float x) { return 1.0f / (1.0f + expf(-x)); }

__global__ void cell_leaf_kernel(const float* __restrict__ buf)
{
    const size_t idx = (size_t)blockIdx.x * blockDim.x + threadIdx.x;
    if (idx >= (size_t)B_ * LVS * H_) return;
    const int n = (int)(idx & (H_ - 1));
    const size_t r = idx >> 9;
    const float* row = buf + r * TH;
    const float i_ = row[n], o_ = row[n + 512], u_ = row[n + 1024];
    const float cn = sigf(i_) * tanhf(u_);
    const float hn = sigf(o_) * tanhf(cn);
    const int b = (int)(r >> 8), leaf = (int)(r & 255);
    const size_t ob = ((size_t)b * NN + leaf) * H_ + n;
    g_h[ob] = hn;
    g_c[ob] = cn;
}

__global__ void cell_level_kernel(const float* __restrict__ buf,
                                  int lm, int off, int off_prev, int total)
{
    const int idx = blockIdx.x * blockDim.x + threadIdx.x;
    if (idx >= total) return;
    const int n = idx & (H_ - 1);
    const int r = idx >> 9;
    const int b = r >> lm;
    const int j = r & ((1 << lm) - 1);
    const float* row = buf + (size_t)r * NC;
    const float i_ = row[n], o_ = row[n + 512], u_ = row[n + 1024];
    const float f0 = row[1536 + n], f1 = row[2048 + n];
    const size_t cb = ((size_t)b * NN + off_prev + 2 * j) * H_ + n;
    const float cf = sigf(f0) * g_c[cb] + sigf(f1) * g_c[cb + H_];
    const float cn = sigf(i_) * tanhf(u_) + cf;
    const float hn = sigf(o_) * tanhf(cn);
    const size_t ob = ((size_t)b * NN + off + j) * H_ + n;
    g_h[ob] = hn;
    g_c[ob] = cn;
}

__global__ void classify_kernel(const float* __restrict__ lw,
                                const float* __restrict__ lb,
                                float* __restrict__ out)
{
    const int t = blockIdx.x * blockDim.x + threadIdx.x;
    if (t >= B_ * NN * 5) return;
    const int node = t / 5, cls = t - node * 5;
    const float4* hr = (const float4*)(g_h + (size_t)node * H_);
    const float4* wr = (const float4*)(lw + (size_t)cls * H_);
    float acc = 0.0f;
#pragma unroll 4
    for (int k = 0; k < 128; k++) {
        const float4 a = hr[k], w = wr[k];
        acc += a.x * w.x + a.y * w.y + a.z * w.z + a.w * w.w;
    }
    out[t] = acc + lb[cls];
}

// -------------------- weight packing / input gather -------------------------
__global__ void pack_wcat_kernel(const float* __restrict__ Uiou,
                                 const float* __restrict__ Uf)
{
    const int idx = blockIdx.x * blockDim.x + threadIdx.x;
    if (idx >= 1024 * NC) return;
    const int k = idx / NC, n = idx - k * NC;
    g_wc[idx] = (n < TH) ? Uiou[(size_t)n * 1024 + k]
                         : Uf[(size_t)(n - TH) * 1024 + k];
}

__global__ void pack_bias_kernel(const float* __restrict__ bi,
                                 const float* __restrict__ bf)
{
    const int n = blockIdx.x * blockDim.x + threadIdx.x;
    if (n < NC) g_bc[n] = (n < TH) ? bi[n] : bf[n - TH];
}

__global__ void pack_wleaf_kernel(const float* __restrict__ W)
{
    const int idx = blockIdx.x * blockDim.x + threadIdx.x;
    if (idx >= XP * TH) return;
    const int k = idx / TH, n = idx - k * TH;
    g_wl[idx] = (k < X_) ? W[(size_t)n * X_ + k] : 0.0f;
}

__global__ void gather_x_kernel(const int* __restrict__ wid,
                                const float* __restrict__ emb)
{
    const int r = blockIdx.x;
    const int c = threadIdx.x;
    if (c < XP)
        g_x[(size_t)r * XP + c] = (c < X_) ? emb[(size_t)wid[r] * X_ + c] : 0.0f;
}

// -------------------- launch --------------------------------------------------
extern "C" void kernel_launch(void* const* d_in, const int* in_sizes, int n_in,
                              void* d_out, int out_size)
{
    const int*   wordid  = (const int*)  d_in[0];
    const float* emb     = (const float*)d_in[1];
    const float* W_iou_w = (const float*)d_in[2];
    const float* W_iou_b = (const float*)d_in[3];
    const float* U_iou_w = (const float*)d_in[4];
    const float* U_iou_b = (const float*)d_in[5];
    const float* U_f_w   = (const float*)d_in[6];
    const float* U_f_b   = (const float*)d_in[7];
    const float* lin_w   = (const float*)d_in[8];
    const float* lin_b   = (const float*)d_in[9];
    float* out = (float*)d_out;

    float *ph, *pc, *pbuf, *px, *pwc, *pwl, *pbc;
    cudaGetSymbolAddress((void**)&ph,  g_h);
    cudaGetSymbolAddress((void**)&pc,  g_c);
    cudaGetSymbolAddress((void**)&pbuf, g_buf);
    cudaGetSymbolAddress((void**)&px,  g_x);
    cudaGetSymbolAddress((void**)&pwc, g_wc);
    cudaGetSymbolAddress((void**)&pwl, g_wl);
    cudaGetSymbolAddress((void**)&pbc, g_bc);
    (void)pc; (void)in_sizes; (void)n_in; (void)out_size;

    // ---- prep: pack weights (K-major) and gather/pad leaf embeddings ----
    pack_wcat_kernel <<<(1024 * NC + 255) / 256, 256>>>(U_iou_w, U_f_w);
    pack_bias_kernel <<<(NC + 255) / 256, 256>>>(U_iou_b, U_f_b);
    pack_wleaf_kernel<<<(XP * TH + 255) / 256, 256>>>(W_iou_w);
    gather_x_kernel  <<<B_ * LVS, 320>>>(wordid, emb);

    // ---- leaves: iou = x @ W_iou^T + b ; cell(c_f = 0) ----
    {
        dim3 gl(TH / 128, (B_ * LVS) / 128);
        sgemm_kernel<<<gl, 256>>>(px, pwl, W_iou_b, pbuf, TH, XP, XP, -1, 0);
        cell_leaf_kernel<<<(B_ * LVS * H_) / 256, 256>>>(pbuf);
    }

    // ---- internal levels (sequential dependency chain) ----
    static const int offs[10] = {0, 256, 384, 448, 480, 496, 504, 508, 510, 511};
    for (int l = 1; l <= 8; l++) {
        const int m = LVS >> l;        // nodes per tree at this level
        const int M = B_ * m;          // GEMM rows
        const int lm = 8 - l;          // log2(m)
        dim3 g(NC / 128, M / 128);
        sgemm_kernel<<<g, 256>>>(ph, pwc, pbc, pbuf, NC, 1024, 0, lm, offs[l - 1]);
        const int total = M * H_;
        cell_level_kernel<<<(total + 255) / 256, 256>>>(pbuf, lm, offs[l], offs[l - 1], total);
    }

    // ---- classifier: logits = h_all @ lin_w^T + lin_b ----
    classify_kernel<<<(B_ * NN * 5 + 255) / 256, 256>>>(lin_w, lin_b, out);
}

// round 3
// speedup vs baseline: 2.0986x; 2.0986x over previous
#include <cuda_runtime.h>
#include <cuda_bf16.h>
#include <cstdint>
#include <cstddef>

// ---------------------------------------------------------------------------
// TreeLSTM via mma.sync (HMMA) bf16 GEMM with hi/lo split compensation:
//   C = Ahi*Bhi + Alo*Bhi + Ahi*Blo   (fp32 register accumulation)
// tcgen05 is unavailable: harness compiles through compute_103 (non-'a') PTX.
// ---------------------------------------------------------------------------

#define B_   256
#define LVS  256
#define H_   512
#define X_   300
#define NN   511
#define TH   1536
#define NC   2560
#define KLF  320          // leaf K padded to multiple of 32

// GEMM tiling
#define BM   128
#define BN   128
#define BK   32
#define SP   40                   // padded smem row stride (bf16 elems)
#define TILEB (128 * SP * 2)      // 10240 B per tile
#define STAGE (4 * TILEB)         // Ah, Al, Bh, Bl
#define NST  3
#define SMEM_BYTES (NST * STAGE)  // 122880

// -------------------- static scratch ----------------------------------------
__device__ float         g_c  [(size_t)B_ * NN * H_];
__device__ float         g_buf[(size_t)B_ * LVS * TH];
__device__ __nv_bfloat16 g_hh [(size_t)B_ * NN * H_];
__device__ __nv_bfloat16 g_hl [(size_t)B_ * NN * H_];
__device__ __nv_bfloat16 g_xh [(size_t)B_ * LVS * KLF];
__device__ __nv_bfloat16 g_xl [(size_t)B_ * LVS * KLF];
__device__ __nv_bfloat16 g_wch[(size_t)NC * 1024];
__device__ __nv_bfloat16 g_wcl[(size_t)NC * 1024];
__device__ __nv_bfloat16 g_wlh[(size_t)TH * KLF];
__device__ __nv_bfloat16 g_wll[(size_t)TH * KLF];
__device__ float         g_bc [NC];

// -------------------- PTX helpers -------------------------------------------
__device__ __forceinline__ uint32_t smem_u32(const void* p) {
    uint32_t a;
    asm("{ .reg .u64 t; cvta.to.shared.u64 t, %1; cvt.u32.u64 %0, t; }"
        : "=r"(a) : "l"(p));
    return a;
}
__device__ __forceinline__ void cp16(uint32_t dst, const void* src) {
    asm volatile("cp.async.cg.shared.global [%0], [%1], 16;" :: "r"(dst), "l"(src));
}
__device__ __forceinline__ void cp_commit() {
    asm volatile("cp.async.commit_group;" ::: "memory");
}
template <int N> __device__ __forceinline__ void cp_wait() {
    asm volatile("cp.async.wait_group %0;" :: "n"(N) : "memory");
}
__device__ __forceinline__ void ldmat4(uint32_t* r, uint32_t addr) {
    asm volatile("ldmatrix.sync.aligned.m8n8.x4.shared.b16 {%0,%1,%2,%3}, [%4];"
                 : "=r"(r[0]), "=r"(r[1]), "=r"(r[2]), "=r"(r[3]) : "r"(addr));
}
__device__ __forceinline__ void mma16816(float* c, const uint32_t* a,
                                         const uint32_t* b) {
    asm volatile(
        "mma.sync.aligned.m16n8k16.row.col.f32.bf16.bf16.f32 "
        "{%0,%1,%2,%3}, {%4,%5,%6,%7}, {%8,%9}, {%0,%1,%2,%3};"
        : "+f"(c[0]), "+f"(c[1]), "+f"(c[2]), "+f"(c[3])
        : "r"(a[0]), "r"(a[1]), "r"(a[2]), "r"(a[3]), "r"(b[0]), "r"(b[1]));
}

// -------------------- HMMA GEMM ---------------------------------------------
// C[M, Ntot] = (Ahi+Alo)[M, K] @ (Bhi+Blo)[Ntot, K]^T + bias   (fp32 out)
// tree_lm >= 0: GEMM row r -> contiguous 1024-elem h_cat of node
//               (b = r>>tree_lm, j = r & (m-1)) at level offset off_prev.
__global__ void __launch_bounds__(256, 1) gemm_mma_kernel(
    const __nv_bfloat16* __restrict__ Ah, const __nv_bfloat16* __restrict__ Al,
    const __nv_bfloat16* __restrict__ Bh, const __nv_bfloat16* __restrict__ Bl,
    const float* __restrict__ bias, float* __restrict__ C,
    int Ntot, int Kel, int nk, int tree_lm, int off_prev)
{
    extern __shared__ char smem[];
    const uint32_t sbase = smem_u32(smem);
    const int t = threadIdx.x;
    const int lane = t & 31, wid = t >> 5;
    const int m0 = blockIdx.y * BM, n0 = blockIdx.x * BN;

    // ---------- loader setup: thread handles rows lr0 and lr0+64, 16B seg lj
    const int lr0 = t >> 2;
    const int lj  = t & 3;
    const uint32_t s0 = (uint32_t)lr0 * (SP * 2) + (uint32_t)lj * 16;
    const uint32_t s1 = s0 + 64 * (SP * 2);
    size_t a0b, a1b;
    {
        const int gr0 = m0 + lr0, gr1 = gr0 + 64;
        if (tree_lm >= 0) {
            const int msk = (1 << tree_lm) - 1;
            a0b = ((size_t)(gr0 >> tree_lm) * NN + off_prev + 2 * (gr0 & msk)) * H_;
            a1b = ((size_t)(gr1 >> tree_lm) * NN + off_prev + 2 * (gr1 & msk)) * H_;
        } else {
            a0b = (size_t)gr0 * Kel;
            a1b = (size_t)gr1 * Kel;
        }
    }
    const char* pAh0 = (const char*)(Ah + a0b);
    const char* pAh1 = (const char*)(Ah + a1b);
    const char* pAl0 = (const char*)(Al + a0b);
    const char* pAl1 = (const char*)(Al + a1b);
    const char* pBh0 = (const char*)(Bh + (size_t)(n0 + lr0) * Kel);
    const char* pBh1 = (const char*)(Bh + (size_t)(n0 + lr0 + 64) * Kel);
    const char* pBl0 = (const char*)(Bl + (size_t)(n0 + lr0) * Kel);
    const char* pBl1 = (const char*)(Bl + (size_t)(n0 + lr0 + 64) * Kel);
    const uint32_t jb = (uint32_t)lj * 16;

#define LOADS(kk, st) do {                                                    \
        const uint32_t sb_ = sbase + (uint32_t)(st) * STAGE;                  \
        const size_t gb_ = (size_t)(kk) * 64 + jb;                            \
        cp16(sb_ + 0 * TILEB + s0, pAh0 + gb_);                               \
        cp16(sb_ + 0 * TILEB + s1, pAh1 + gb_);                               \
        cp16(sb_ + 1 * TILEB + s0, pAl0 + gb_);                               \
        cp16(sb_ + 1 * TILEB + s1, pAl1 + gb_);                               \
        cp16(sb_ + 2 * TILEB + s0, pBh0 + gb_);                               \
        cp16(sb_ + 2 * TILEB + s1, pBh1 + gb_);                               \
        cp16(sb_ + 3 * TILEB + s0, pBl0 + gb_);                               \
        cp16(sb_ + 3 * TILEB + s1, pBl1 + gb_);                               \
        cp_commit();                                                          \
    } while (0)

    // ---------- compute setup: 4x2 warp grid, 32x64 warp tile ----------
    const int warp_m = (wid & 3) * 32, warp_n = (wid >> 2) * 64;
    // A frag lane addr: row = warp_m + mi*16 + (lane&15), col = ks*16 + (lane>>4)*8
    const uint32_t aoff = ((uint32_t)(warp_m + (lane & 15)) * SP
                           + ((uint32_t)(lane >> 4) << 3)) * 2;
    // B frag lane addr: row = warp_n + nj*16 + (lane>>4)*8 + (lane&7),
    //                   col = ks*16 + ((lane>>3)&1)*8
    const uint32_t boff = ((uint32_t)(warp_n + ((lane >> 4) << 3) + (lane & 7)) * SP
                           + (((uint32_t)(lane >> 3) & 1) << 3)) * 2;

    float acc[2][8][4];
#pragma unroll
    for (int mi = 0; mi < 2; mi++)
#pragma unroll
        for (int nj = 0; nj < 8; nj++)
#pragma unroll
            for (int q = 0; q < 4; q++) acc[mi][nj][q] = 0.0f;

    LOADS(0, 0);
    LOADS(1, 1);

    int st = 0;
    for (int k = 0; k < nk; k++) {
        if (k + 2 < nk) LOADS(k + 2, (k + 2) % NST);
        else            cp_commit();
        cp_wait<2>();
        __syncthreads();

        const uint32_t sb = sbase + (uint32_t)st * STAGE;
#pragma unroll
        for (int ks = 0; ks < 2; ks++) {
            uint32_t ah[2][4], al[2][4], bh[4][4], bl[4][4];
#pragma unroll
            for (int mi = 0; mi < 2; mi++) {
                const uint32_t o = aoff + (uint32_t)mi * (16 * SP * 2) + ks * 32;
                ldmat4(ah[mi], sb + 0 * TILEB + o);
                ldmat4(al[mi], sb + 1 * TILEB + o);
            }
#pragma unroll
            for (int nj = 0; nj < 4; nj++) {
                const uint32_t o = boff + (uint32_t)nj * (16 * SP * 2) + ks * 32;
                ldmat4(bh[nj], sb + 2 * TILEB + o);
                ldmat4(bl[nj], sb + 3 * TILEB + o);
            }
#pragma unroll
            for (int mi = 0; mi < 2; mi++)
#pragma unroll
                for (int nj = 0; nj < 4; nj++) {
                    mma16816(acc[mi][2 * nj],     ah[mi], &bh[nj][0]);
                    mma16816(acc[mi][2 * nj + 1], ah[mi], &bh[nj][2]);
                    mma16816(acc[mi][2 * nj],     al[mi], &bh[nj][0]);
                    mma16816(acc[mi][2 * nj + 1], al[mi], &bh[nj][2]);
                    mma16816(acc[mi][2 * nj],     ah[mi], &bl[nj][0]);
                    mma16816(acc[mi][2 * nj + 1], ah[mi], &bl[nj][2]);
                }
        }
        __syncthreads();
        st = (st + 1) % NST;
    }

    // ---------- epilogue ----------
    const int er = lane >> 2, ec = (lane & 3) * 2;
#pragma unroll
    for (int mi = 0; mi < 2; mi++) {
        const int rbase = m0 + warp_m + mi * 16 + er;
#pragma unroll
        for (int nj = 0; nj < 8; nj++) {
            const int col = n0 + warp_n + nj * 8 + ec;
            const float b0 = bias[col], b1 = bias[col + 1];
            float2 v;
            v.x = acc[mi][nj][0] + b0;
            v.y = acc[mi][nj][1] + b1;
            *(float2*)&C[(size_t)rbase * Ntot + col] = v;
            v.x = acc[mi][nj][2] + b0;
            v.y = acc[mi][nj][3] + b1;
            *(float2*)&C[(size_t)(rbase + 8) * Ntot + col] = v;
        }
    }
#undef LOADS
}

// -------------------- cell / epilogue kernels -------------------------------
__device__ __forceinline__ float sigf(float x) { return 1.0f / (1.0f + expf(-x)); }

__device__ __forceinline__ void store_h(size_t ob, float hn) {
    const __nv_bfloat16 hi = __float2bfloat16(hn);
    g_hh[ob] = hi;
    g_hl[ob] = __float2bfloat16(hn - __bfloat162float(hi));
}

__global__ void cell_leaf_kernel(const float* __restrict__ buf)
{
    const size_t idx = (size_t)blockIdx.x * blockDim.x + threadIdx.x;
    if (idx >= (size_t)B_ * LVS * H_) return;
    const int n = (int)(idx & (H_ - 1));
    const size_t r = idx >> 9;
    const float* row = buf + r * TH;
    const float i_ = row[n], o_ = row[n + 512], u_ = row[n + 1024];
    const float cn = sigf(i_) * tanhf(u_);
    const float hn = sigf(o_) * tanhf(cn);
    const int b = (int)(r >> 8), leaf = (int)(r & 255);
    const size_t ob = ((size_t)b * NN + leaf) * H_ + n;
    g_c[ob] = cn;
    store_h(ob, hn);
}

__global__ void cell_level_kernel(const float* __restrict__ buf,
                                  int lm, int off, int off_prev, int total)
{
    const int idx = blockIdx.x * blockDim.x + threadIdx.x;
    if (idx >= total) return;
    const int n = idx & (H_ - 1);
    const int r = idx >> 9;
    const int b = r >> lm;
    const int j = r & ((1 << lm) - 1);
    const float* row = buf + (size_t)r * NC;
    const float i_ = row[n], o_ = row[n + 512], u_ = row[n + 1024];
    const float f0 = row[1536 + n], f1 = row[2048 + n];
    const size_t cb = ((size_t)b * NN + off_prev + 2 * j) * H_ + n;
    const float cf = sigf(f0) * g_c[cb] + sigf(f1) * g_c[cb + H_];
    const float cn = sigf(i_) * tanhf(u_) + cf;
    const float hn = sigf(o_) * tanhf(cn);
    const size_t ob = ((size_t)b * NN + off + j) * H_ + n;
    g_c[ob] = cn;
    store_h(ob, hn);
}

__global__ void classify_kernel(const float* __restrict__ lw,
                                const float* __restrict__ lb,
                                float* __restrict__ out)
{
    const int node = blockIdx.x * blockDim.x + threadIdx.x;
    if (node >= B_ * NN) return;
    const __nv_bfloat162* hh = (const __nv_bfloat162*)(g_hh + (size_t)node * H_);
    const __nv_bfloat162* hl = (const __nv_bfloat162*)(g_hl + (size_t)node * H_);
    float acc[5] = {0.f, 0.f, 0.f, 0.f, 0.f};
#pragma unroll 4
    for (int k2 = 0; k2 < 256; k2++) {
        const float2 a = __bfloat1622float2(hh[k2]);
        const float2 b = __bfloat1622float2(hl[k2]);
        const float h0 = a.x + b.x, h1 = a.y + b.y;
#pragma unroll
        for (int c = 0; c < 5; c++)
            acc[c] += h0 * lw[c * H_ + 2 * k2] + h1 * lw[c * H_ + 2 * k2 + 1];
    }
#pragma unroll
    for (int c = 0; c < 5; c++)
        out[(size_t)node * 5 + c] = acc[c] + lb[c];
}

// -------------------- packing / gather --------------------------------------
__device__ __forceinline__ void split_bf16(float v, __nv_bfloat16* hi,
                                           __nv_bfloat16* lo, size_t i) {
    const __nv_bfloat16 h = __float2bfloat16(v);
    hi[i] = h;
    lo[i] = __float2bfloat16(v - __bfloat162float(h));
}

__global__ void pack_wcat_kernel(const float* __restrict__ Uiou,
                                 const float* __restrict__ Uf)
{
    const int idx = blockIdx.x * blockDim.x + threadIdx.x;
    if (idx >= NC * 1024) return;
    const int n = idx >> 10, k = idx & 1023;
    const float v = (n < TH) ? Uiou[(size_t)n * 1024 + k]
                             : Uf[(size_t)(n - TH) * 1024 + k];
    split_bf16(v, g_wch, g_wcl, idx);
}

__global__ void pack_wleaf_kernel(const float* __restrict__ W)
{
    const int idx = blockIdx.x * blockDim.x + threadIdx.x;
    if (idx >= TH * KLF) return;
    const int n = idx / KLF, k = idx - n * KLF;
    const float v = (k < X_) ? W[(size_t)n * X_ + k] : 0.0f;
    split_bf16(v, g_wlh, g_wll, idx);
}

__global__ void pack_bias_kernel(const float* __restrict__ bi,
                                 const float* __restrict__ bf)
{
    const int n = blockIdx.x * blockDim.x + threadIdx.x;
    if (n < NC) g_bc[n] = (n < TH) ? bi[n] : bf[n - TH];
}

__global__ void gather_x_kernel(const int* __restrict__ wid,
                                const float* __restrict__ emb)
{
    const int r = blockIdx.x;
    const int c = threadIdx.x;
    if (c >= KLF) return;
    const float v = (c < X_) ? emb[(size_t)wid[r] * X_ + c] : 0.0f;
    split_bf16(v, g_xh, g_xl, (size_t)r * KLF + c);
}

// -------------------- launch ------------------------------------------------
extern "C" void kernel_launch(void* const* d_in, const int* in_sizes, int n_in,
                              void* d_out, int out_size)
{
    const int*   wordid  = (const int*)  d_in[0];
    const float* emb     = (const float*)d_in[1];
    const float* W_iou_w = (const float*)d_in[2];
    const float* W_iou_b = (const float*)d_in[3];
    const float* U_iou_w = (const float*)d_in[4];
    const float* U_iou_b = (const float*)d_in[5];
    const float* U_f_w   = (const float*)d_in[6];
    const float* U_f_b   = (const float*)d_in[7];
    const float* lin_w   = (const float*)d_in[8];
    const float* lin_b   = (const float*)d_in[9];
    float* out = (float*)d_out;
    (void)in_sizes; (void)n_in; (void)out_size;

    float *pc, *pbuf, *pbc;
    __nv_bfloat16 *phh, *phl, *pxh, *pxl, *pwch, *pwcl, *pwlh, *pwll;
    cudaGetSymbolAddress((void**)&pc,   g_c);
    cudaGetSymbolAddress((void**)&pbuf, g_buf);
    cudaGetSymbolAddress((void**)&pbc,  g_bc);
    cudaGetSymbolAddress((void**)&phh,  g_hh);
    cudaGetSymbolAddress((void**)&phl,  g_hl);
    cudaGetSymbolAddress((void**)&pxh,  g_xh);
    cudaGetSymbolAddress((void**)&pxl,  g_xl);
    cudaGetSymbolAddress((void**)&pwch, g_wch);
    cudaGetSymbolAddress((void**)&pwcl, g_wcl);
    cudaGetSymbolAddress((void**)&pwlh, g_wlh);
    cudaGetSymbolAddress((void**)&pwll, g_wll);
    (void)pc;

    cudaFuncSetAttribute(gemm_mma_kernel,
                         cudaFuncAttributeMaxDynamicSharedMemorySize, SMEM_BYTES);

    // ---- prep ----
    pack_wcat_kernel <<<(NC * 1024 + 255) / 256, 256>>>(U_iou_w, U_f_w);
    pack_wleaf_kernel<<<(TH * KLF + 255) / 256, 256>>>(W_iou_w);
    pack_bias_kernel <<<(NC + 255) / 256, 256>>>(U_iou_b, U_f_b);
    gather_x_kernel  <<<B_ * LVS, KLF>>>(wordid, emb);

    // ---- leaves ----
    {
        dim3 g(TH / BN, (B_ * LVS) / BM);
        gemm_mma_kernel<<<g, 256, SMEM_BYTES>>>(pxh, pxl, pwlh, pwll, W_iou_b,
                                                pbuf, TH, KLF, KLF / BK, -1, 0);
        cell_leaf_kernel<<<(B_ * LVS * H_) / 256, 256>>>(pbuf);
    }

    // ---- internal levels ----
    static const int offs[10] = {0, 256, 384, 448, 480, 496, 504, 508, 510, 511};
    for (int l = 1; l <= 8; l++) {
        const int m = LVS >> l;
        const int M = B_ * m;
        const int lm = 8 - l;
        dim3 g(NC / BN, M / BM);
        gemm_mma_kernel<<<g, 256, SMEM_BYTES>>>(phh, phl, pwch, pwcl, pbc,
                                                pbuf, NC, 1024, 1024 / BK,
                                                lm, offs[l - 1]);
        const int total = M * H_;
        cell_level_kernel<<<(total + 255) / 256, 256>>>(pbuf, lm, offs[l],
                                                        offs[l - 1], total);
    }

    // ---- classifier ----
    classify_kernel<<<(B_ * NN + 127) / 128, 128>>>(lin_w, lin_b, out);
}

// round 4
// speedup vs baseline: 2.1939x; 1.0454x over previous
#include <cuda_runtime.h>
#include <cuda_bf16.h>
#include <cstdint>
#include <cstddef>

// ---------------------------------------------------------------------------
// TreeLSTM via mma.sync (HMMA) bf16 GEMM with hi/lo split compensation:
//   C = Ahi*Bhi + Alo*Bhi + Ahi*Blo   (fp32 register accumulation)
// R4: product-major MMA ordering (breaks same-accumulator dependency chains),
//     single __syncthreads per k-iteration.
// ---------------------------------------------------------------------------

#define B_   256
#define LVS  256
#define H_   512
#define X_   300
#define NN   511
#define TH   1536
#define NC   2560
#define KLF  320          // leaf K padded to multiple of 32

// GEMM tiling
#define BM   128
#define BN   128
#define BK   32
#define SP   40                   // padded smem row stride (bf16 elems)
#define TILEB (128 * SP * 2)      // 10240 B per tile
#define STAGE (4 * TILEB)         // Ah, Al, Bh, Bl
#define NST  3
#define SMEM_BYTES (NST * STAGE)  // 122880

// -------------------- static scratch ----------------------------------------
__device__ float         g_c  [(size_t)B_ * NN * H_];
__device__ float         g_buf[(size_t)B_ * LVS * TH];
__device__ __nv_bfloat16 g_hh [(size_t)B_ * NN * H_];
__device__ __nv_bfloat16 g_hl [(size_t)B_ * NN * H_];
__device__ __nv_bfloat16 g_xh [(size_t)B_ * LVS * KLF];
__device__ __nv_bfloat16 g_xl [(size_t)B_ * LVS * KLF];
__device__ __nv_bfloat16 g_wch[(size_t)NC * 1024];
__device__ __nv_bfloat16 g_wcl[(size_t)NC * 1024];
__device__ __nv_bfloat16 g_wlh[(size_t)TH * KLF];
__device__ __nv_bfloat16 g_wll[(size_t)TH * KLF];
__device__ float         g_bc [NC];

// -------------------- PTX helpers -------------------------------------------
__device__ __forceinline__ uint32_t smem_u32(const void* p) {
    uint32_t a;
    asm("{ .reg .u64 t; cvta.to.shared.u64 t, %1; cvt.u32.u64 %0, t; }"
        : "=r"(a) : "l"(p));
    return a;
}
__device__ __forceinline__ void cp16(uint32_t dst, const void* src) {
    asm volatile("cp.async.cg.shared.global [%0], [%1], 16;" :: "r"(dst), "l"(src));
}
__device__ __forceinline__ void cp_commit() {
    asm volatile("cp.async.commit_group;" ::: "memory");
}
template <int N> __device__ __forceinline__ void cp_wait() {
    asm volatile("cp.async.wait_group %0;" :: "n"(N) : "memory");
}
__device__ __forceinline__ void ldmat4(uint32_t* r, uint32_t addr) {
    asm volatile("ldmatrix.sync.aligned.m8n8.x4.shared.b16 {%0,%1,%2,%3}, [%4];"
                 : "=r"(r[0]), "=r"(r[1]), "=r"(r[2]), "=r"(r[3]) : "r"(addr));
}
__device__ __forceinline__ void mma16816(float* c, const uint32_t* a,
                                         const uint32_t* b) {
    asm volatile(
        "mma.sync.aligned.m16n8k16.row.col.f32.bf16.bf16.f32 "
        "{%0,%1,%2,%3}, {%4,%5,%6,%7}, {%8,%9}, {%0,%1,%2,%3};"
        : "+f"(c[0]), "+f"(c[1]), "+f"(c[2]), "+f"(c[3])
        : "r"(a[0]), "r"(a[1]), "r"(a[2]), "r"(a[3]), "r"(b[0]), "r"(b[1]));
}

// -------------------- HMMA GEMM ---------------------------------------------
// C[M, Ntot] = (Ahi+Alo)[M, K] @ (Bhi+Blo)[Ntot, K]^T + bias   (fp32 out)
// tree_lm >= 0: GEMM row r -> contiguous 1024-elem h_cat of node
//               (b = r>>tree_lm, j = r & (m-1)) at level offset off_prev.
__global__ void __launch_bounds__(256, 1) gemm_mma_kernel(
    const __nv_bfloat16* __restrict__ Ah, const __nv_bfloat16* __restrict__ Al,
    const __nv_bfloat16* __restrict__ Bh, const __nv_bfloat16* __restrict__ Bl,
    const float* __restrict__ bias, float* __restrict__ C,
    int Ntot, int Kel, int nk, int tree_lm, int off_prev)
{
    extern __shared__ char smem[];
    const uint32_t sbase = smem_u32(smem);
    const int t = threadIdx.x;
    const int lane = t & 31, wid = t >> 5;
    const int m0 = blockIdx.y * BM, n0 = blockIdx.x * BN;

    // ---------- loader setup: thread handles rows lr0 and lr0+64, 16B seg lj
    const int lr0 = t >> 2;
    const int lj  = t & 3;
    const uint32_t s0 = (uint32_t)lr0 * (SP * 2) + (uint32_t)lj * 16;
    const uint32_t s1 = s0 + 64 * (SP * 2);
    size_t a0b, a1b;
    {
        const int gr0 = m0 + lr0, gr1 = gr0 + 64;
        if (tree_lm >= 0) {
            const int msk = (1 << tree_lm) - 1;
            a0b = ((size_t)(gr0 >> tree_lm) * NN + off_prev + 2 * (gr0 & msk)) * H_;
            a1b = ((size_t)(gr1 >> tree_lm) * NN + off_prev + 2 * (gr1 & msk)) * H_;
        } else {
            a0b = (size_t)gr0 * Kel;
            a1b = (size_t)gr1 * Kel;
        }
    }
    const char* pAh0 = (const char*)(Ah + a0b);
    const char* pAh1 = (const char*)(Ah + a1b);
    const char* pAl0 = (const char*)(Al + a0b);
    const char* pAl1 = (const char*)(Al + a1b);
    const char* pBh0 = (const char*)(Bh + (size_t)(n0 + lr0) * Kel);
    const char* pBh1 = (const char*)(Bh + (size_t)(n0 + lr0 + 64) * Kel);
    const char* pBl0 = (const char*)(Bl + (size_t)(n0 + lr0) * Kel);
    const char* pBl1 = (const char*)(Bl + (size_t)(n0 + lr0 + 64) * Kel);
    const uint32_t jb = (uint32_t)lj * 16;

#define LOADS(kk, st) do {                                                    \
        const uint32_t sb_ = sbase + (uint32_t)(st) * STAGE;                  \
        const size_t gb_ = (size_t)(kk) * 64 + jb;                            \
        cp16(sb_ + 0 * TILEB + s0, pAh0 + gb_);                               \
        cp16(sb_ + 0 * TILEB + s1, pAh1 + gb_);                               \
        cp16(sb_ + 1 * TILEB + s0, pAl0 + gb_);                               \
        cp16(sb_ + 1 * TILEB + s1, pAl1 + gb_);                               \
        cp16(sb_ + 2 * TILEB + s0, pBh0 + gb_);                               \
        cp16(sb_ + 2 * TILEB + s1, pBh1 + gb_);                               \
        cp16(sb_ + 3 * TILEB + s0, pBl0 + gb_);                               \
        cp16(sb_ + 3 * TILEB + s1, pBl1 + gb_);                               \
        cp_commit();                                                          \
    } while (0)

    // ---------- compute setup: 4x2 warp grid, 32x64 warp tile ----------
    const int warp_m = (wid & 3) * 32, warp_n = (wid >> 2) * 64;
    const uint32_t aoff = ((uint32_t)(warp_m + (lane & 15)) * SP
                           + ((uint32_t)(lane >> 4) << 3)) * 2;
    const uint32_t boff = ((uint32_t)(warp_n + ((lane >> 4) << 3) + (lane & 7)) * SP
                           + (((uint32_t)(lane >> 3) & 1) << 3)) * 2;

    float acc[2][8][4];
#pragma unroll
    for (int mi = 0; mi < 2; mi++)
#pragma unroll
        for (int nj = 0; nj < 8; nj++)
#pragma unroll
            for (int q = 0; q < 4; q++) acc[mi][nj][q] = 0.0f;

    LOADS(0, 0);
    LOADS(1, 1);

    int st = 0;
    for (int k = 0; k < nk; k++) {
        cp_wait<1>();
        __syncthreads();
        if (k + 2 < nk) LOADS(k + 2, (k + 2) % NST);

        const uint32_t sb = sbase + (uint32_t)st * STAGE;
#pragma unroll
        for (int ks = 0; ks < 2; ks++) {
            uint32_t ah[2][4], al[2][4], bh[4][4], bl[4][4];
#pragma unroll
            for (int mi = 0; mi < 2; mi++) {
                const uint32_t o = aoff + (uint32_t)mi * (16 * SP * 2) + ks * 32;
                ldmat4(ah[mi], sb + 0 * TILEB + o);
                ldmat4(al[mi], sb + 1 * TILEB + o);
            }
#pragma unroll
            for (int nj = 0; nj < 4; nj++) {
                const uint32_t o = boff + (uint32_t)nj * (16 * SP * 2) + ks * 32;
                ldmat4(bh[nj], sb + 2 * TILEB + o);
                ldmat4(bl[nj], sb + 3 * TILEB + o);
            }
            // product-major issue: same-accumulator reuse distance = 16 MMAs
#pragma unroll
            for (int mi = 0; mi < 2; mi++)
#pragma unroll
                for (int nj = 0; nj < 4; nj++) {
                    mma16816(acc[mi][2 * nj],     ah[mi], &bh[nj][0]);
                    mma16816(acc[mi][2 * nj + 1], ah[mi], &bh[nj][2]);
                }
#pragma unroll
            for (int mi = 0; mi < 2; mi++)
#pragma unroll
                for (int nj = 0; nj < 4; nj++) {
                    mma16816(acc[mi][2 * nj],     al[mi], &bh[nj][0]);
                    mma16816(acc[mi][2 * nj + 1], al[mi], &bh[nj][2]);
                }
#pragma unroll
            for (int mi = 0; mi < 2; mi++)
#pragma unroll
                for (int nj = 0; nj < 4; nj++) {
                    mma16816(acc[mi][2 * nj],     ah[mi], &bl[nj][0]);
                    mma16816(acc[mi][2 * nj + 1], ah[mi], &bl[nj][2]);
                }
        }
        st = (st + 1 == NST) ? 0 : st + 1;
    }

    // ---------- epilogue ----------
    const int er = lane >> 2, ec = (lane & 3) * 2;
#pragma unroll
    for (int mi = 0; mi < 2; mi++) {
        const int rbase = m0 + warp_m + mi * 16 + er;
#pragma unroll
        for (int nj = 0; nj < 8; nj++) {
            const int col = n0 + warp_n + nj * 8 + ec;
            const float b0 = bias[col], b1 = bias[col + 1];
            float2 v;
            v.x = acc[mi][nj][0] + b0;
            v.y = acc[mi][nj][1] + b1;
            *(float2*)&C[(size_t)rbase * Ntot + col] = v;
            v.x = acc[mi][nj][2] + b0;
            v.y = acc[mi][nj][3] + b1;
            *(float2*)&C[(size_t)(rbase + 8) * Ntot + col] = v;
        }
    }
#undef LOADS
}

// -------------------- cell / epilogue kernels -------------------------------
__device__ __forceinline__ float sigf(float x) { return 1.0f / (1.0f + expf(-x)); }

__device__ __forceinline__ void store_h(size_t ob, float hn) {
    const __nv_bfloat16 hi = __float2bfloat16(hn);
    g_hh[ob] = hi;
    g_hl[ob] = __float2bfloat16(hn - __bfloat162float(hi));
}

__global__ void cell_leaf_kernel(const float* __restrict__ buf)
{
    const size_t idx = (size_t)blockIdx.x * blockDim.x + threadIdx.x;
    if (idx >= (size_t)B_ * LVS * H_) return;
    const int n = (int)(idx & (H_ - 1));
    const size_t r = idx >> 9;
    const float* row = buf + r * TH;
    const float i_ = row[n], o_ = row[n + 512], u_ = row[n + 1024];
    const float cn = sigf(i_) * tanhf(u_);
    const float hn = sigf(o_) * tanhf(cn);
    const int b = (int)(r >> 8), leaf = (int)(r & 255);
    const size_t ob = ((size_t)b * NN + leaf) * H_ + n;
    g_c[ob] = cn;
    store_h(ob, hn);
}

__global__ void cell_level_kernel(const float* __restrict__ buf,
                                  int lm, int off, int off_prev, int total)
{
    const int idx = blockIdx.x * blockDim.x + threadIdx.x;
    if (idx >= total) return;
    const int n = idx & (H_ - 1);
    const int r = idx >> 9;
    const int b = r >> lm;
    const int j = r & ((1 << lm) - 1);
    const float* row = buf + (size_t)r * NC;
    const float i_ = row[n], o_ = row[n + 512], u_ = row[n + 1024];
    const float f0 = row[1536 + n], f1 = row[2048 + n];
    const size_t cb = ((size_t)b * NN + off_prev + 2 * j) * H_ + n;
    const float cf = sigf(f0) * g_c[cb] + sigf(f1) * g_c[cb + H_];
    const float cn = sigf(i_) * tanhf(u_) + cf;
    const float hn = sigf(o_) * tanhf(cn);
    const size_t ob = ((size_t)b * NN + off + j) * H_ + n;
    g_c[ob] = cn;
    store_h(ob, hn);
}

__global__ void classify_kernel(const float* __restrict__ lw,
                                const float* __restrict__ lb,
                                float* __restrict__ out)
{
    const int node = blockIdx.x * blockDim.x + threadIdx.x;
    if (node >= B_ * NN) return;
    const __nv_bfloat162* hh = (const __nv_bfloat162*)(g_hh + (size_t)node * H_);
    const __nv_bfloat162* hl = (const __nv_bfloat162*)(g_hl + (size_t)node * H_);
    float acc[5] = {0.f, 0.f, 0.f, 0.f, 0.f};
#pragma unroll 4
    for (int k2 = 0; k2 < 256; k2++) {
        const float2 a = __bfloat1622float2(hh[k2]);
        const float2 b = __bfloat1622float2(hl[k2]);
        const float h0 = a.x + b.x, h1 = a.y + b.y;
#pragma unroll
        for (int c = 0; c < 5; c++)
            acc[c] += h0 * lw[c * H_ + 2 * k2] + h1 * lw[c * H_ + 2 * k2 + 1];
    }
#pragma unroll
    for (int c = 0; c < 5; c++)
        out[(size_t)node * 5 + c] = acc[c] + lb[c];
}

// -------------------- packing / gather --------------------------------------
__device__ __forceinline__ void split_bf16(float v, __nv_bfloat16* hi,
                                           __nv_bfloat16* lo, size_t i) {
    const __nv_bfloat16 h = __float2bfloat16(v);
    hi[i] = h;
    lo[i] = __float2bfloat16(v - __bfloat162float(h));
}

__global__ void pack_wcat_kernel(const float* __restrict__ Uiou,
                                 const float* __restrict__ Uf)
{
    const int idx = blockIdx.x * blockDim.x + threadIdx.x;
    if (idx >= NC * 1024) return;
    const int n = idx >> 10, k = idx & 1023;
    const float v = (n < TH) ? Uiou[(size_t)n * 1024 + k]
                             : Uf[(size_t)(n - TH) * 1024 + k];
    split_bf16(v, g_wch, g_wcl, idx);
}

__global__ void pack_wleaf_kernel(const float* __restrict__ W)
{
    const int idx = blockIdx.x * blockDim.x + threadIdx.x;
    if (idx >= TH * KLF) return;
    const int n = idx / KLF, k = idx - n * KLF;
    const float v = (k < X_) ? W[(size_t)n * X_ + k] : 0.0f;
    split_bf16(v, g_wlh, g_wll, idx);
}

__global__ void pack_bias_kernel(const float* __restrict__ bi,
                                 const float* __restrict__ bf)
{
    const int n = blockIdx.x * blockDim.x + threadIdx.x;
    if (n < NC) g_bc[n] = (n < TH) ? bi[n] : bf[n - TH];
}

__global__ void gather_x_kernel(const int* __restrict__ wid,
                                const float* __restrict__ emb)
{
    const int r = blockIdx.x;
    const int c = threadIdx.x;
    if (c >= KLF) return;
    const float v = (c < X_) ? emb[(size_t)wid[r] * X_ + c] : 0.0f;
    split_bf16(v, g_xh, g_xl, (size_t)r * KLF + c);
}

// -------------------- launch ------------------------------------------------
extern "C" void kernel_launch(void* const* d_in, const int* in_sizes, int n_in,
                              void* d_out, int out_size)
{
    const int*   wordid  = (const int*)  d_in[0];
    const float* emb     = (const float*)d_in[1];
    const float* W_iou_w = (const float*)d_in[2];
    const float* W_iou_b = (const float*)d_in[3];
    const float* U_iou_w = (const float*)d_in[4];
    const float* U_iou_b = (const float*)d_in[5];
    const float* U_f_w   = (const float*)d_in[6];
    const float* U_f_b   = (const float*)d_in[7];
    const float* lin_w   = (const float*)d_in[8];
    const float* lin_b   = (const float*)d_in[9];
    float* out = (float*)d_out;
    (void)in_sizes; (void)n_in; (void)out_size;

    float *pc, *pbuf, *pbc;
    __nv_bfloat16 *phh, *phl, *pxh, *pxl, *pwch, *pwcl, *pwlh, *pwll;
    cudaGetSymbolAddress((void**)&pc,   g_c);
    cudaGetSymbolAddress((void**)&pbuf, g_buf);
    cudaGetSymbolAddress((void**)&pbc,  g_bc);
    cudaGetSymbolAddress((void**)&phh,  g_hh);
    cudaGetSymbolAddress((void**)&phl,  g_hl);
    cudaGetSymbolAddress((void**)&pxh,  g_xh);
    cudaGetSymbolAddress((void**)&pxl,  g_xl);
    cudaGetSymbolAddress((void**)&pwch, g_wch);
    cudaGetSymbolAddress((void**)&pwcl, g_wcl);
    cudaGetSymbolAddress((void**)&pwlh, g_wlh);
    cudaGetSymbolAddress((void**)&pwll, g_wll);
    (void)pc;

    cudaFuncSetAttribute(gemm_mma_kernel,
                         cudaFuncAttributeMaxDynamicSharedMemorySize, SMEM_BYTES);

    // ---- prep ----
    pack_wcat_kernel <<<(NC * 1024 + 255) / 256, 256>>>(U_iou_w, U_f_w);
    pack_wleaf_kernel<<<(TH * KLF + 255) / 256, 256>>>(W_iou_w);
    pack_bias_kernel <<<(NC + 255) / 256, 256>>>(U_iou_b, U_f_b);
    gather_x_kernel  <<<B_ * LVS, KLF>>>(wordid, emb);

    // ---- leaves ----
    {
        dim3 g(TH / BN, (B_ * LVS) / BM);
        gemm_mma_kernel<<<g, 256, SMEM_BYTES>>>(pxh, pxl, pwlh, pwll, W_iou_b,
                                                pbuf, TH, KLF, KLF / BK, -1, 0);
        cell_leaf_kernel<<<(B_ * LVS * H_) / 256, 256>>>(pbuf);
    }

    // ---- internal levels ----
    static const int offs[10] = {0, 256, 384, 448, 480, 496, 504, 508, 510, 511};
    for (int l = 1; l <= 8; l++) {
        const int m = LVS >> l;
        const int M = B_ * m;
        const int lm = 8 - l;
        dim3 g(NC / BN, M / BM);
        gemm_mma_kernel<<<g, 256, SMEM_BYTES>>>(phh, phl, pwch, pwcl, pbc,
                                                pbuf, NC, 1024, 1024 / BK,
                                                lm, offs[l - 1]);
        const int total = M * H_;
        cell_level_kernel<<<(total + 255) / 256, 256>>>(pbuf, lm, offs[l],
                                                        offs[l - 1], total);
    }

    // ---- classifier ----
    classify_kernel<<<(B_ * NN + 127) / 128, 128>>>(lin_w, lin_b, out);
}